// round 11
// baseline (speedup 1.0000x reference)
#include <cuda_runtime.h>
#include <cuda_fp16.h>
#include <cstdint>

#define BB 8
#define NN 1024
#define FIN 64
#define FOUT 128
#define HH 4
#define DD 32
#define TI 32
#define LOG2E 1.4426950408889634f

// device-global scratch. Transposed + permuted h: [b][f][j_perm], fp16.
// Within each 32-node group, slot s holds node j = 2*(s>>3) + (((s&7)>>1)<<3) + (s&1).
__device__ __align__(16) __half g_hT[BB * FOUT * NN];
__device__ float g_src[BB * NN * HH];           // pre-scaled by log2e
__device__ float g_dst[BB * NN * HH];
__device__ float g_lpart[2 * BB * NN * HH];     // partial softmax denominators

__device__ __forceinline__ float ex2f(float x) {
    float r;
    asm("ex2.approx.ftz.f32 %0, %1;" : "=f"(r) : "f"(x));
    return r;
}
__device__ __forceinline__ void mma16816(float* d, unsigned a0, unsigned a1,
                                         unsigned a2, unsigned a3,
                                         unsigned b0, unsigned b1) {
    asm volatile(
        "mma.sync.aligned.m16n8k16.row.col.f32.f16.f16.f32 "
        "{%0,%1,%2,%3},{%4,%5,%6,%7},{%8,%9},{%0,%1,%2,%3};"
        : "+f"(d[0]), "+f"(d[1]), "+f"(d[2]), "+f"(d[3])
        : "r"(a0), "r"(a1), "r"(a2), "r"(a3), "r"(b0), "r"(b1));
}

// ---------------- Kernel 1: h = x@W (f32x2, 2x4 register block, 256 thr) ----------------
// block = (b, 32-node group, 64-feature half). grid = 512, 256 threads.
// Also zeroes `out` (2 float4 per thread) so kB can atomically accumulate.
__global__ __launch_bounds__(256) void gat_k1(
    const float* __restrict__ x, const float* __restrict__ W, const float* __restrict__ a,
    float* __restrict__ out)
{
    __shared__ float sW[FIN * 68];       // 17.4 KB
    __shared__ float sx[32 * 68];        // 8.7 KB
    __shared__ __half sh[32 * 72];       // 4.5 KB
    __shared__ float sa[HH * 2 * DD];    // 1 KB

    int t     = threadIdx.x;
    int b     = blockIdx.x >> 6;
    int n0    = ((blockIdx.x >> 1) & 31) << 5;
    int fhalf = blockIdx.x & 1;

    // zero out: 512 blocks x 256 threads x 2 float4 = 1M floats
    {
        float4 z = make_float4(0.f, 0.f, 0.f, 0.f);
        size_t o4 = ((size_t)blockIdx.x * 256 + t) * 2;
        ((float4*)out)[o4]     = z;
        ((float4*)out)[o4 + 1] = z;
    }

    // cooperative loads (256 threads)
    {
        const float4* W4 = (const float4*)W;
        #pragma unroll
        for (int s = 0; s < 4; s++) {
            int idx = t + (s << 8);                 // 64 rows x 16 float4
            int row = idx >> 4, c4 = idx & 15;
            *(float4*)(sW + row * 68 + (c4 << 2)) = W4[(row << 5) + (fhalf << 4) + c4];
        }
        const float4* x4 = (const float4*)(x + ((b << 10) + n0) * FIN);
        #pragma unroll
        for (int s = 0; s < 2; s++) {
            int idx = t + (s << 8);                 // 32 rows x 16 float4
            int row = idx >> 4, c4 = idx & 15;
            *(float4*)(sx + row * 68 + (c4 << 2)) = x4[idx];
        }
        if (t < 64) ((float4*)sa)[t] = ((const float4*)a)[t];
    }
    __syncthreads();

    // GEMM: thread = (rowgroup rg = t>>4 -> rows 2rg,2rg+1 ; ci = t&15 -> cols 4ci..4ci+3)
    int rg = t >> 4;
    int ci = t & 15;
    int r0 = rg << 1;
    int c0 = ci << 2;
    unsigned long long a0[2], a1[2];
    a0[0] = a0[1] = a1[0] = a1[1] = 0ull;
    {
        const float* x0p = sx + r0 * 68;
        const float* x1p = x0p + 68;
        #pragma unroll 8
        for (int k = 0; k < FIN; k++) {
            float xv0 = x0p[k], xv1 = x1p[k];
            unsigned long long xx0, xx1;
            asm("mov.b64 %0, {%1, %1};" : "=l"(xx0) : "f"(xv0));
            asm("mov.b64 %0, {%1, %1};" : "=l"(xx1) : "f"(xv1));
            const unsigned long long* wp = (const unsigned long long*)(sW + k * 68 + c0);
            #pragma unroll
            for (int q = 0; q < 2; q++) {
                unsigned long long wv = wp[q];
                asm("fma.rn.f32x2 %0, %1, %2, %0;" : "+l"(a0[q]) : "l"(xx0), "l"(wv));
                asm("fma.rn.f32x2 %0, %1, %2, %0;" : "+l"(a1[q]) : "l"(xx1), "l"(wv));
            }
        }
    }
    // unpack
    float f0[4], f1[4];
    #pragma unroll
    for (int q = 0; q < 2; q++) {
        asm("mov.b64 {%0, %1}, %2;" : "=f"(f0[2*q]), "=f"(f0[2*q+1]) : "l"(a0[q]));
        asm("mov.b64 {%0, %1}, %2;" : "=f"(f1[2*q]), "=f"(f1[2*q+1]) : "l"(a1[q]));
    }

    // e_src/e_dst from accumulators (head half hl = ci>>3, 8 ci per head)
    {
        int hl = ci >> 3;
        int head = (fhalf << 1) + hl;
        int dbase = (ci & 7) << 2;                  // head-local feature offset
        const float* ap = sa + head * 64;           // src weights
        const float* aq = ap + 32;                  // dst weights
        float ps0 = 0.f, pd0 = 0.f, ps1 = 0.f, pd1 = 0.f;
        #pragma unroll
        for (int cc = 0; cc < 4; cc++) {
            float w1 = ap[dbase + cc], w2 = aq[dbase + cc];
            ps0 = fmaf(f0[cc], w1, ps0); pd0 = fmaf(f0[cc], w2, pd0);
            ps1 = fmaf(f1[cc], w1, ps1); pd1 = fmaf(f1[cc], w2, pd1);
        }
        ps0 += __shfl_xor_sync(0xffffffffu, ps0, 1); ps0 += __shfl_xor_sync(0xffffffffu, ps0, 2);
        ps0 += __shfl_xor_sync(0xffffffffu, ps0, 4);
        pd0 += __shfl_xor_sync(0xffffffffu, pd0, 1); pd0 += __shfl_xor_sync(0xffffffffu, pd0, 2);
        pd0 += __shfl_xor_sync(0xffffffffu, pd0, 4);
        ps1 += __shfl_xor_sync(0xffffffffu, ps1, 1); ps1 += __shfl_xor_sync(0xffffffffu, ps1, 2);
        ps1 += __shfl_xor_sync(0xffffffffu, ps1, 4);
        pd1 += __shfl_xor_sync(0xffffffffu, pd1, 1); pd1 += __shfl_xor_sync(0xffffffffu, pd1, 2);
        pd1 += __shfl_xor_sync(0xffffffffu, pd1, 4);
        if ((ci & 7) == 0) {
            int gnr = (b << 10) + n0 + r0;
            g_src[gnr * HH + head]        = ps0 * LOG2E;
            g_dst[gnr * HH + head]        = pd0 * LOG2E;
            g_src[(gnr + 1) * HH + head]  = ps1 * LOG2E;
            g_dst[(gnr + 1) * HH + head]  = pd1 * LOG2E;
        }
    }

    // fp16 store to sh
    {
        union { __half2 h2[2]; uint2 v; } u0, u1;
        #pragma unroll
        for (int q = 0; q < 2; q++) {
            u0.h2[q] = __floats2half2_rn(f0[2*q], f0[2*q+1]);
            u1.h2[q] = __floats2half2_rn(f1[2*q], f1[2*q+1]);
        }
        *(uint2*)(sh + r0 * 72 + c0)       = u0.v;
        *(uint2*)(sh + (r0 + 1) * 72 + c0) = u1.v;
    }
    __syncthreads();

    // permuted transposed fp16 store: thread = (f_local = t>>2, hseg = t&3)
    {
        int f_local = t >> 2, hseg = t & 3;
        int f = (fhalf << 6) + f_local;
        union { __half h[8]; uint4 v; } u;
        #pragma unroll
        for (int k2 = 0; k2 < 8; k2++) {
            int j = 2 * hseg + ((k2 >> 1) << 3) + (k2 & 1);   // slot = hseg*8+k2
            u.h[k2] = sh[j * 72 + f_local];
        }
        size_t gbase = (((size_t)(b << 7) + f) << 10) + n0 + (hseg << 3);
        *(uint4*)(g_hT + gbase) = u.v;
    }
}

// ---------------- Kernel A: partial softmax denominators (branchless, fronted loads) ----------------
__global__ __launch_bounds__(256) void gat_kA(const int* __restrict__ adj)
{
    __shared__ float s_srcA[128];
    int b = blockIdx.y, z = blockIdx.z;
    int i0 = blockIdx.x << 5;
    int jbase = z << 9;
    int t = threadIdx.x, w = t >> 5, lane = t & 31;

    if (t < 128) s_srcA[t] = g_src[((b << 10) + i0) * 4 + t];
    __syncthreads();

    const float4* gd4 = (const float4*)g_dst + (b << 10) + jbase;

    #pragma unroll
    for (int rr = 0; rr < 4; rr++) {
        int i = w + (rr << 3);
        int gi = i0 + i;
        const int* adjrow = adj + (size_t)gi * NN + jbase;
        // front all adj loads for this row (MLP 8 on the L2-latency path)
        int2 avv[8];
        #pragma unroll
        for (int jj = 0; jj < 8; jj++)
            avv[jj] = __ldg((const int2*)(adjrow + (lane << 1) + (jj << 6)));

        float s0 = s_srcA[i*4+0], s1 = s_srcA[i*4+1], s2 = s_srcA[i*4+2], s3 = s_srcA[i*4+3];
        float l0 = 0.f, l1 = 0.f, l2 = 0.f, l3 = 0.f;
        #pragma unroll
        for (int jj = 0; jj < 8; jj++) {
            int j = (lane << 1) + (jj << 6);
            float ma = avv[jj].x ? 1.f : 0.f;
            float mb = avv[jj].y ? 1.f : 0.f;
            float4 dA = __ldg(gd4 + j);
            float4 dB = __ldg(gd4 + j + 1);
            float e;
            e = s0 + dA.x; e = fmaxf(e, 0.2f*e); l0 = fmaf(ex2f(e), ma, l0);
            e = s1 + dA.y; e = fmaxf(e, 0.2f*e); l1 = fmaf(ex2f(e), ma, l1);
            e = s2 + dA.z; e = fmaxf(e, 0.2f*e); l2 = fmaf(ex2f(e), ma, l2);
            e = s3 + dA.w; e = fmaxf(e, 0.2f*e); l3 = fmaf(ex2f(e), ma, l3);
            e = s0 + dB.x; e = fmaxf(e, 0.2f*e); l0 = fmaf(ex2f(e), mb, l0);
            e = s1 + dB.y; e = fmaxf(e, 0.2f*e); l1 = fmaf(ex2f(e), mb, l1);
            e = s2 + dB.z; e = fmaxf(e, 0.2f*e); l2 = fmaf(ex2f(e), mb, l2);
            e = s3 + dB.w; e = fmaxf(e, 0.2f*e); l3 = fmaf(ex2f(e), mb, l3);
        }
        #pragma unroll
        for (int off = 16; off; off >>= 1) {
            l0 += __shfl_xor_sync(0xffffffffu, l0, off);
            l1 += __shfl_xor_sync(0xffffffffu, l1, off);
            l2 += __shfl_xor_sync(0xffffffffu, l2, off);
            l3 += __shfl_xor_sync(0xffffffffu, l3, off);
        }
        if (lane == 0) {
            float* lp = g_lpart + ((size_t)(z * BB + b) << 12) + ((size_t)gi << 2);
            lp[0] = l0; lp[1] = l1; lp[2] = l2; lp[3] = l3;
        }
    }
}

// ---------------- Kernel B: q + avg + HMMA on one j-half, atomic out ----------------
#define RSTR 96
#define S_HB    24576
#define S_SRC   49152
#define S_LINV  49664
#define S_EMPTY 50176
#define SMEMB   50304

__global__ __launch_bounds__(256, 4) void gat_kB(
    const int* __restrict__ adj, const float* __restrict__ ew,
    float* __restrict__ out, float* __restrict__ avg)
{
    extern __shared__ char smem[];
    __half* s_qA    = (__half*)smem;
    __half* s_hB    = (__half*)(smem + S_HB);
    float*  s_src   = (float*)(smem + S_SRC);
    float*  s_linv  = (float*)(smem + S_LINV);
    int*    s_empty = (int*)(smem + S_EMPTY);

    int b  = blockIdx.y, z = blockIdx.z;
    int i0 = blockIdx.x * TI;
    int t = threadIdx.x, w = t >> 5, lane = t & 31;

    if (t < 128) {
        s_src[t] = g_src[((b << 10) + i0) * 4 + t];
        size_t off = ((size_t)b << 12) + (((size_t)i0) << 2) + t;
        float l = g_lpart[off] + g_lpart[((size_t)BB << 12) + off];
        int emp = !(l > 0.f);
        s_linv[t] = emp ? 1.f : 1.f / l;
        if ((t & 3) == 0) s_empty[t >> 2] = emp;
    }
    __syncthreads();

    float dA0[4] = {0,0,0,0}, dA1[4] = {0,0,0,0};
    float dB0[4] = {0,0,0,0}, dB1[4] = {0,0,0,0};
    int h  = w >> 1;
    int nh = w & 1;
    int g  = lane >> 2;
    int tq = lane & 3;
    int ncol = (h << 5) + (nh << 4);

    int qgrp = lane >> 4, qk2 = lane & 15;
    int qoff = (qgrp << 5) + ((((qk2 & 3) << 2) + (qk2 >> 2)) << 1);

    const float4* gd4 = (const float4*)g_dst + (b << 10);

    for (int cl = 0; cl < 8; cl++) {
        int c = (z << 3) + cl;
        int jl = lane << 1;
        int j  = (c << 6) + jl;
        __syncthreads();

        // stage h-tile gmem -> smem
        #pragma unroll
        for (int s = 0; s < 4; s++) {
            int idx = t + (s << 8);
            int f = idx >> 3, seg = idx & 7;
            *(uint4*)(s_hB + f * RSTR + (seg << 3)) =
                __ldg((const uint4*)(g_hT + (((size_t)(b << 7) + f) << 10) + (c << 6) + (seg << 3)));
        }

        // front the adj/ew loads for all 4 rows (MLP 8 on the L2-latency path)
        int2   avv[4];
        float2 eww[4];
        #pragma unroll
        for (int rr = 0; rr < 4; rr++) {
            int gi = i0 + w + (rr << 3);
            avv[rr] = __ldg((const int2*)(adj + (size_t)gi * NN + j));
            eww[rr] = __ldg((const float2*)(ew + (size_t)gi * NN + j));
        }

        // q-compute + avg write
        #pragma unroll
        for (int rr = 0; rr < 4; rr++) {
            int i = w + (rr << 3);
            int gi = i0 + i;
            float* avgrow = avg + ((size_t)(b * NN) + gi) * NN;
            float2 ew2 = eww[rr];
            float va, vb;
            if (!s_empty[i]) {                      // warp-uniform branch
                float sv[4], lv[4];
                #pragma unroll
                for (int q = 0; q < 4; q++) { sv[q] = s_src[i*4+q]; lv[q] = s_linv[i*4+q]; }
                float4 dA = __ldg(gd4 + j);
                float4 dB = __ldg(gd4 + j + 1);
                float ma = avv[rr].x ? 1.f : 0.f;
                float mb = avv[rr].y ? 1.f : 0.f;
                float dAv[4] = {dA.x, dA.y, dA.z, dA.w};
                float dBv[4] = {dB.x, dB.y, dB.z, dB.w};
                va = 0.f; vb = 0.f;
                #pragma unroll
                for (int hh = 0; hh < 4; hh++) {
                    float e, qa, qb;
                    e = sv[hh] + dAv[hh]; e = fmaxf(e, 0.2f*e); qa = ex2f(e) * ma;
                    e = sv[hh] + dBv[hh]; e = fmaxf(e, 0.2f*e); qb = ex2f(e) * mb;
                    va = fmaf(qa, lv[hh], va);
                    vb = fmaf(qb, lv[hh], vb);
                    __half2 hq = __floats2half2_rn(qa * ew2.x, qb * ew2.y);
                    *(__half2*)(s_qA + ((hh << 5) + i) * RSTR + qoff) = hq;
                }
            } else {                                // empty row: uniform 1/N
                __half2 hq = __floats2half2_rn(ew2.x * (1.f/1024.f), ew2.y * (1.f/1024.f));
                #pragma unroll
                for (int hh = 0; hh < 4; hh++)
                    *(__half2*)(s_qA + ((hh << 5) + i) * RSTR + qoff) = hq;
                va = 4.f * (1.f/1024.f); vb = va;
            }
            *(float2*)(avgrow + j) = make_float2(0.25f * va * ew2.x, 0.25f * vb * ew2.y);
        }
        __syncthreads();

        // HMMA
        #pragma unroll
        for (int ktt = 0; ktt < 2; ktt++) {
            int fo = (ktt << 5) + (tq << 3);
            uint4 aT0g  = *(uint4*)(s_qA + ((h << 5) + g)          * RSTR + fo);
            uint4 aT0g8 = *(uint4*)(s_qA + ((h << 5) + g + 8)      * RSTR + fo);
            uint4 aT1g  = *(uint4*)(s_qA + ((h << 5) + 16 + g)     * RSTR + fo);
            uint4 aT1g8 = *(uint4*)(s_qA + ((h << 5) + 16 + g + 8) * RSTR + fo);
            uint4 bh0 = *(uint4*)(s_hB + (ncol + g)     * RSTR + fo);
            uint4 bh1 = *(uint4*)(s_hB + (ncol + g + 8) * RSTR + fo);
            mma16816(dA0, aT0g.x, aT0g8.x, aT0g.y, aT0g8.y, bh0.x, bh0.y);
            mma16816(dA1, aT0g.x, aT0g8.x, aT0g.y, aT0g8.y, bh1.x, bh1.y);
            mma16816(dB0, aT1g.x, aT1g8.x, aT1g.y, aT1g8.y, bh0.x, bh0.y);
            mma16816(dB1, aT1g.x, aT1g8.x, aT1g.y, aT1g8.y, bh1.x, bh1.y);
            mma16816(dA0, aT0g.z, aT0g8.z, aT0g.w, aT0g8.w, bh0.z, bh0.w);
            mma16816(dA1, aT0g.z, aT0g8.z, aT0g.w, aT0g8.w, bh1.z, bh1.w);
            mma16816(dB0, aT1g.z, aT1g8.z, aT1g.w, aT1g8.w, bh0.z, bh0.w);
            mma16816(dB1, aT1g.z, aT1g8.z, aT1g.w, aT1g8.w, bh1.z, bh1.w);
        }
    }

    // epilogue: normalize + atomic-accumulate (out pre-zeroed by k1; 2 adds per element)
    {
        int col = ncol + (tq << 1);
        float li0  = s_linv[g * 4 + h];
        float li8  = s_linv[(g + 8) * 4 + h];
        float li16 = s_linv[(16 + g) * 4 + h];
        float li24 = s_linv[(24 + g) * 4 + h];
        size_t r0  = ((size_t)((b << 10) + i0 + g)) << 7;
        float* o0 = out + r0 + col;
        atomicAdd(o0,     dA0[0]*li0);  atomicAdd(o0 + 1,  dA0[1]*li0);
        atomicAdd(o0 + 8, dA1[0]*li0);  atomicAdd(o0 + 9,  dA1[1]*li0);
        float* o8 = out + r0 + (8 << 7) + col;
        atomicAdd(o8,     dA0[2]*li8);  atomicAdd(o8 + 1,  dA0[3]*li8);
        atomicAdd(o8 + 8, dA1[2]*li8);  atomicAdd(o8 + 9,  dA1[3]*li8);
        float* o16 = out + r0 + (16 << 7) + col;
        atomicAdd(o16,     dB0[0]*li16); atomicAdd(o16 + 1, dB0[1]*li16);
        atomicAdd(o16 + 8, dB1[0]*li16); atomicAdd(o16 + 9, dB1[1]*li16);
        float* o24 = out + r0 + (24 << 7) + col;
        atomicAdd(o24,     dB0[2]*li24); atomicAdd(o24 + 1, dB0[3]*li24);
        atomicAdd(o24 + 8, dB1[2]*li24); atomicAdd(o24 + 9, dB1[3]*li24);
    }
}

extern "C" void kernel_launch(void* const* d_in, const int* in_sizes, int n_in,
                              void* d_out, int out_size)
{
    (void)in_sizes; (void)n_in; (void)out_size;
    const float* x   = (const float*)d_in[0];
    const int*   adj = (const int*)d_in[1];
    const float* ew  = (const float*)d_in[2];
    const float* W   = (const float*)d_in[3];
    const float* a   = (const float*)d_in[4];
    float* out = (float*)d_out;                   // [B,N,128]
    float* avg = out + (size_t)BB * NN * FOUT;    // [B,N,N]

    cudaFuncSetAttribute(gat_kB, cudaFuncAttributeMaxDynamicSharedMemorySize, SMEMB);

    gat_k1<<<BB * 32 * 2, 256>>>(x, W, a, out);
    gat_kA<<<dim3(NN / 32, BB, 2), 256>>>(adj);
    gat_kB<<<dim3(NN / TI, BB, 2), 256, SMEMB>>>(adj, ew, out, avg);
}

// round 12
// speedup vs baseline: 1.1091x; 1.1091x over previous
#include <cuda_runtime.h>
#include <cuda_fp16.h>
#include <cstdint>

#define BB 8
#define NN 1024
#define FIN 64
#define FOUT 128
#define HH 4
#define DD 32
#define TI 32
#define LOG2E 1.4426950408889634f

// device-global scratch. Transposed + permuted h: [b][f][j_perm], fp16.
// Within each 32-node group, slot s holds node j = 2*(s>>3) + (((s&7)>>1)<<3) + (s&1).
__device__ __align__(16) __half g_hT[BB * FOUT * NN];
__device__ float g_src[BB * NN * HH];           // pre-scaled by log2e
__device__ float g_dst[BB * NN * HH];
__device__ float g_lpart[2 * BB * NN * HH];     // partial softmax denominators

__device__ __forceinline__ float ex2f(float x) {
    float r;
    asm("ex2.approx.ftz.f32 %0, %1;" : "=f"(r) : "f"(x));
    return r;
}
__device__ __forceinline__ void mma16816(float* d, unsigned a0, unsigned a1,
                                         unsigned a2, unsigned a3,
                                         unsigned b0, unsigned b1) {
    asm volatile(
        "mma.sync.aligned.m16n8k16.row.col.f32.f16.f16.f32 "
        "{%0,%1,%2,%3},{%4,%5,%6,%7},{%8,%9},{%0,%1,%2,%3};"
        : "+f"(d[0]), "+f"(d[1]), "+f"(d[2]), "+f"(d[3])
        : "r"(a0), "r"(a1), "r"(a2), "r"(a3), "r"(b0), "r"(b1));
}

// ---------------- Kernel 1: h = x@W (f32x2, 2x4 register block, 256 thr) ----------------
// block = (b, 32-node group, 64-feature half). grid = 512, 256 threads.
// Also zeroes `out` (2 float4 per thread) so kB can atomically accumulate.
__global__ __launch_bounds__(256) void gat_k1(
    const float* __restrict__ x, const float* __restrict__ W, const float* __restrict__ a,
    float* __restrict__ out)
{
    __shared__ float sW[FIN * 68];       // 17.4 KB
    __shared__ float sx[32 * 68];        // 8.7 KB
    __shared__ __half sh[32 * 72];       // 4.5 KB
    __shared__ float sa[HH * 2 * DD];    // 1 KB

    int t     = threadIdx.x;
    int b     = blockIdx.x >> 6;
    int n0    = ((blockIdx.x >> 1) & 31) << 5;
    int fhalf = blockIdx.x & 1;

    // zero out: 512 blocks x 256 threads x 2 float4 = 1M floats
    {
        float4 z = make_float4(0.f, 0.f, 0.f, 0.f);
        size_t o4 = ((size_t)blockIdx.x * 256 + t) * 2;
        ((float4*)out)[o4]     = z;
        ((float4*)out)[o4 + 1] = z;
    }

    // cooperative loads (256 threads)
    {
        const float4* W4 = (const float4*)W;
        #pragma unroll
        for (int s = 0; s < 4; s++) {
            int idx = t + (s << 8);                 // 64 rows x 16 float4
            int row = idx >> 4, c4 = idx & 15;
            *(float4*)(sW + row * 68 + (c4 << 2)) = W4[(row << 5) + (fhalf << 4) + c4];
        }
        const float4* x4 = (const float4*)(x + ((b << 10) + n0) * FIN);
        #pragma unroll
        for (int s = 0; s < 2; s++) {
            int idx = t + (s << 8);                 // 32 rows x 16 float4
            int row = idx >> 4, c4 = idx & 15;
            *(float4*)(sx + row * 68 + (c4 << 2)) = x4[idx];
        }
        if (t < 64) ((float4*)sa)[t] = ((const float4*)a)[t];
    }
    __syncthreads();

    // GEMM: thread = (rowgroup rg = t>>4 -> rows 2rg,2rg+1 ; ci = t&15 -> cols 4ci..4ci+3)
    int rg = t >> 4;
    int ci = t & 15;
    int r0 = rg << 1;
    int c0 = ci << 2;
    unsigned long long a0[2], a1[2];
    a0[0] = a0[1] = a1[0] = a1[1] = 0ull;
    {
        const float* x0p = sx + r0 * 68;
        const float* x1p = x0p + 68;
        #pragma unroll 8
        for (int k = 0; k < FIN; k++) {
            float xv0 = x0p[k], xv1 = x1p[k];
            unsigned long long xx0, xx1;
            asm("mov.b64 %0, {%1, %1};" : "=l"(xx0) : "f"(xv0));
            asm("mov.b64 %0, {%1, %1};" : "=l"(xx1) : "f"(xv1));
            const unsigned long long* wp = (const unsigned long long*)(sW + k * 68 + c0);
            #pragma unroll
            for (int q = 0; q < 2; q++) {
                unsigned long long wv = wp[q];
                asm("fma.rn.f32x2 %0, %1, %2, %0;" : "+l"(a0[q]) : "l"(xx0), "l"(wv));
                asm("fma.rn.f32x2 %0, %1, %2, %0;" : "+l"(a1[q]) : "l"(xx1), "l"(wv));
            }
        }
    }
    // unpack
    float f0[4], f1[4];
    #pragma unroll
    for (int q = 0; q < 2; q++) {
        asm("mov.b64 {%0, %1}, %2;" : "=f"(f0[2*q]), "=f"(f0[2*q+1]) : "l"(a0[q]));
        asm("mov.b64 {%0, %1}, %2;" : "=f"(f1[2*q]), "=f"(f1[2*q+1]) : "l"(a1[q]));
    }

    // e_src/e_dst from accumulators (head half hl = ci>>3, 8 ci per head)
    {
        int hl = ci >> 3;
        int head = (fhalf << 1) + hl;
        int dbase = (ci & 7) << 2;                  // head-local feature offset
        const float* ap = sa + head * 64;           // src weights
        const float* aq = ap + 32;                  // dst weights
        float ps0 = 0.f, pd0 = 0.f, ps1 = 0.f, pd1 = 0.f;
        #pragma unroll
        for (int cc = 0; cc < 4; cc++) {
            float w1 = ap[dbase + cc], w2 = aq[dbase + cc];
            ps0 = fmaf(f0[cc], w1, ps0); pd0 = fmaf(f0[cc], w2, pd0);
            ps1 = fmaf(f1[cc], w1, ps1); pd1 = fmaf(f1[cc], w2, pd1);
        }
        ps0 += __shfl_xor_sync(0xffffffffu, ps0, 1); ps0 += __shfl_xor_sync(0xffffffffu, ps0, 2);
        ps0 += __shfl_xor_sync(0xffffffffu, ps0, 4);
        pd0 += __shfl_xor_sync(0xffffffffu, pd0, 1); pd0 += __shfl_xor_sync(0xffffffffu, pd0, 2);
        pd0 += __shfl_xor_sync(0xffffffffu, pd0, 4);
        ps1 += __shfl_xor_sync(0xffffffffu, ps1, 1); ps1 += __shfl_xor_sync(0xffffffffu, ps1, 2);
        ps1 += __shfl_xor_sync(0xffffffffu, ps1, 4);
        pd1 += __shfl_xor_sync(0xffffffffu, pd1, 1); pd1 += __shfl_xor_sync(0xffffffffu, pd1, 2);
        pd1 += __shfl_xor_sync(0xffffffffu, pd1, 4);
        if ((ci & 7) == 0) {
            int gnr = (b << 10) + n0 + r0;
            g_src[gnr * HH + head]        = ps0 * LOG2E;
            g_dst[gnr * HH + head]        = pd0 * LOG2E;
            g_src[(gnr + 1) * HH + head]  = ps1 * LOG2E;
            g_dst[(gnr + 1) * HH + head]  = pd1 * LOG2E;
        }
    }

    // fp16 store to sh
    {
        union { __half2 h2[2]; uint2 v; } u0, u1;
        #pragma unroll
        for (int q = 0; q < 2; q++) {
            u0.h2[q] = __floats2half2_rn(f0[2*q], f0[2*q+1]);
            u1.h2[q] = __floats2half2_rn(f1[2*q], f1[2*q+1]);
        }
        *(uint2*)(sh + r0 * 72 + c0)       = u0.v;
        *(uint2*)(sh + (r0 + 1) * 72 + c0) = u1.v;
    }
    __syncthreads();

    // permuted transposed fp16 store: thread = (f_local = t>>2, hseg = t&3)
    {
        int f_local = t >> 2, hseg = t & 3;
        int f = (fhalf << 6) + f_local;
        union { __half h[8]; uint4 v; } u;
        #pragma unroll
        for (int k2 = 0; k2 < 8; k2++) {
            int j = 2 * hseg + ((k2 >> 1) << 3) + (k2 & 1);   // slot = hseg*8+k2
            u.h[k2] = sh[j * 72 + f_local];
        }
        size_t gbase = (((size_t)(b << 7) + f) << 10) + n0 + (hseg << 3);
        *(uint4*)(g_hT + gbase) = u.v;
    }
}

// ---------------- Kernel A: partial softmax denominators (branchless) ----------------
__global__ __launch_bounds__(256) void gat_kA(const int* __restrict__ adj)
{
    __shared__ float s_srcA[128];
    int b = blockIdx.y, z = blockIdx.z;
    int i0 = blockIdx.x << 5;
    int jbase = z << 9;
    int t = threadIdx.x, w = t >> 5, lane = t & 31;

    if (t < 128) s_srcA[t] = g_src[((b << 10) + i0) * 4 + t];
    __syncthreads();

    const float4* gd4 = (const float4*)g_dst + (b << 10) + jbase;

    #pragma unroll
    for (int rr = 0; rr < 4; rr++) {
        int i = w + (rr << 3);
        int gi = i0 + i;
        const int* adjrow = adj + (size_t)gi * NN + jbase;
        float s0 = s_srcA[i*4+0], s1 = s_srcA[i*4+1], s2 = s_srcA[i*4+2], s3 = s_srcA[i*4+3];
        float l0 = 0.f, l1 = 0.f, l2 = 0.f, l3 = 0.f;
        #pragma unroll 4
        for (int jj = 0; jj < 8; jj++) {
            int j = (lane << 1) + (jj << 6);
            int2 av = __ldg((const int2*)(adjrow + j));
            float ma = av.x ? 1.f : 0.f;
            float mb = av.y ? 1.f : 0.f;
            float4 dA = __ldg(gd4 + j);
            float4 dB = __ldg(gd4 + j + 1);
            float e;
            e = s0 + dA.x; e = fmaxf(e, 0.2f*e); l0 = fmaf(ex2f(e), ma, l0);
            e = s1 + dA.y; e = fmaxf(e, 0.2f*e); l1 = fmaf(ex2f(e), ma, l1);
            e = s2 + dA.z; e = fmaxf(e, 0.2f*e); l2 = fmaf(ex2f(e), ma, l2);
            e = s3 + dA.w; e = fmaxf(e, 0.2f*e); l3 = fmaf(ex2f(e), ma, l3);
            e = s0 + dB.x; e = fmaxf(e, 0.2f*e); l0 = fmaf(ex2f(e), mb, l0);
            e = s1 + dB.y; e = fmaxf(e, 0.2f*e); l1 = fmaf(ex2f(e), mb, l1);
            e = s2 + dB.z; e = fmaxf(e, 0.2f*e); l2 = fmaf(ex2f(e), mb, l2);
            e = s3 + dB.w; e = fmaxf(e, 0.2f*e); l3 = fmaf(ex2f(e), mb, l3);
        }
        #pragma unroll
        for (int off = 16; off; off >>= 1) {
            l0 += __shfl_xor_sync(0xffffffffu, l0, off);
            l1 += __shfl_xor_sync(0xffffffffu, l1, off);
            l2 += __shfl_xor_sync(0xffffffffu, l2, off);
            l3 += __shfl_xor_sync(0xffffffffu, l3, off);
        }
        if (lane == 0) {
            float* lp = g_lpart + ((size_t)(z * BB + b) << 12) + ((size_t)gi << 2);
            lp[0] = l0; lp[1] = l1; lp[2] = l2; lp[3] = l3;
        }
    }
}

// ---------------- Kernel B: q + avg + HMMA on one j-half, atomic out ----------------
#define RSTR 96
#define S_HB    24576
#define S_SRC   49152
#define S_LINV  49664
#define S_EMPTY 50176
#define SMEMB   50304

__global__ __launch_bounds__(256, 4) void gat_kB(
    const int* __restrict__ adj, const float* __restrict__ ew,
    float* __restrict__ out, float* __restrict__ avg)
{
    extern __shared__ char smem[];
    __half* s_qA    = (__half*)smem;
    __half* s_hB    = (__half*)(smem + S_HB);
    float*  s_src   = (float*)(smem + S_SRC);
    float*  s_linv  = (float*)(smem + S_LINV);
    int*    s_empty = (int*)(smem + S_EMPTY);

    int b  = blockIdx.y, z = blockIdx.z;
    int i0 = blockIdx.x * TI;
    int t = threadIdx.x, w = t >> 5, lane = t & 31;

    if (t < 128) {
        s_src[t] = g_src[((b << 10) + i0) * 4 + t];
        size_t off = ((size_t)b << 12) + (((size_t)i0) << 2) + t;
        float l = g_lpart[off] + g_lpart[((size_t)BB << 12) + off];
        int emp = !(l > 0.f);
        s_linv[t] = emp ? 1.f : 1.f / l;
        if ((t & 3) == 0) s_empty[t >> 2] = emp;
    }
    __syncthreads();

    float dA0[4] = {0,0,0,0}, dA1[4] = {0,0,0,0};
    float dB0[4] = {0,0,0,0}, dB1[4] = {0,0,0,0};
    int h  = w >> 1;
    int nh = w & 1;
    int g  = lane >> 2;
    int tq = lane & 3;
    int ncol = (h << 5) + (nh << 4);

    int qgrp = lane >> 4, qk2 = lane & 15;
    int qoff = (qgrp << 5) + ((((qk2 & 3) << 2) + (qk2 >> 2)) << 1);

    const float4* gd4 = (const float4*)g_dst + (b << 10);

    for (int cl = 0; cl < 8; cl++) {
        int c = (z << 3) + cl;
        __syncthreads();

        #pragma unroll
        for (int s = 0; s < 4; s++) {
            int idx = t + (s << 8);
            int f = idx >> 3, seg = idx & 7;
            *(uint4*)(s_hB + f * RSTR + (seg << 3)) =
                __ldg((const uint4*)(g_hT + (((size_t)(b << 7) + f) << 10) + (c << 6) + (seg << 3)));
        }

        #pragma unroll
        for (int rr = 0; rr < 4; rr++) {
            int i = w + (rr << 3);
            int gi = i0 + i;
            const int*   adjrow = adj + (size_t)gi * NN;
            const float* ewrow  = ew  + (size_t)gi * NN;
            float* avgrow = avg + ((size_t)(b * NN) + gi) * NN;
            float sv[4], lv[4];
            #pragma unroll
            for (int q = 0; q < 4; q++) { sv[q] = s_src[i*4+q]; lv[q] = s_linv[i*4+q]; }
            int emp = s_empty[i];
            int jl = lane << 1;
            int j  = (c << 6) + jl;
            int2   av  = __ldg((const int2*)(adjrow + j));
            float2 ew2 = __ldg((const float2*)(ewrow + j));
            float4 dA = __ldg(gd4 + j);
            float4 dB = __ldg(gd4 + j + 1);
            float ma = av.x ? 1.f : 0.f;
            float mb = av.y ? 1.f : 0.f;
            float dAv[4] = {dA.x, dA.y, dA.z, dA.w};
            float dBv[4] = {dB.x, dB.y, dB.z, dB.w};
            float va = 0.f, vb = 0.f;
            #pragma unroll
            for (int hh = 0; hh < 4; hh++) {
                float e, qa, qb;
                e = sv[hh] + dAv[hh]; e = fmaxf(e, 0.2f*e); qa = ex2f(e) * ma;
                e = sv[hh] + dBv[hh]; e = fmaxf(e, 0.2f*e); qb = ex2f(e) * mb;
                qa = emp ? (1.f / 1024.f) : qa;
                qb = emp ? (1.f / 1024.f) : qb;
                va = fmaf(qa, lv[hh], va);
                vb = fmaf(qb, lv[hh], vb);
                __half2 hq = __floats2half2_rn(qa * ew2.x, qb * ew2.y);
                *(__half2*)(s_qA + ((hh << 5) + i) * RSTR + qoff) = hq;
            }
            *(float2*)(avgrow + j) = make_float2(0.25f * va * ew2.x, 0.25f * vb * ew2.y);
        }
        __syncthreads();

        #pragma unroll
        for (int ktt = 0; ktt < 2; ktt++) {
            int fo = (ktt << 5) + (tq << 3);
            uint4 aT0g  = *(uint4*)(s_qA + ((h << 5) + g)          * RSTR + fo);
            uint4 aT0g8 = *(uint4*)(s_qA + ((h << 5) + g + 8)      * RSTR + fo);
            uint4 aT1g  = *(uint4*)(s_qA + ((h << 5) + 16 + g)     * RSTR + fo);
            uint4 aT1g8 = *(uint4*)(s_qA + ((h << 5) + 16 + g + 8) * RSTR + fo);
            uint4 bh0 = *(uint4*)(s_hB + (ncol + g)     * RSTR + fo);
            uint4 bh1 = *(uint4*)(s_hB + (ncol + g + 8) * RSTR + fo);
            mma16816(dA0, aT0g.x, aT0g8.x, aT0g.y, aT0g8.y, bh0.x, bh0.y);
            mma16816(dA1, aT0g.x, aT0g8.x, aT0g.y, aT0g8.y, bh1.x, bh1.y);
            mma16816(dB0, aT1g.x, aT1g8.x, aT1g.y, aT1g8.y, bh0.x, bh0.y);
            mma16816(dB1, aT1g.x, aT1g8.x, aT1g.y, aT1g8.y, bh1.x, bh1.y);
            mma16816(dA0, aT0g.z, aT0g8.z, aT0g.w, aT0g8.w, bh0.z, bh0.w);
            mma16816(dA1, aT0g.z, aT0g8.z, aT0g.w, aT0g8.w, bh1.z, bh1.w);
            mma16816(dB0, aT1g.z, aT1g8.z, aT1g.w, aT1g8.w, bh0.z, bh0.w);
            mma16816(dB1, aT1g.z, aT1g8.z, aT1g.w, aT1g8.w, bh1.z, bh1.w);
        }
    }

    // epilogue: normalize + atomic-accumulate (out pre-zeroed by k1; 2 adds per element)
    {
        int col = ncol + (tq << 1);
        float li0  = s_linv[g * 4 + h];
        float li8  = s_linv[(g + 8) * 4 + h];
        float li16 = s_linv[(16 + g) * 4 + h];
        float li24 = s_linv[(24 + g) * 4 + h];
        size_t r0  = ((size_t)((b << 10) + i0 + g)) << 7;
        float* o0 = out + r0 + col;
        atomicAdd(o0,     dA0[0]*li0);  atomicAdd(o0 + 1,  dA0[1]*li0);
        atomicAdd(o0 + 8, dA1[0]*li0);  atomicAdd(o0 + 9,  dA1[1]*li0);
        float* o8 = out + r0 + (8 << 7) + col;
        atomicAdd(o8,     dA0[2]*li8);  atomicAdd(o8 + 1,  dA0[3]*li8);
        atomicAdd(o8 + 8, dA1[2]*li8);  atomicAdd(o8 + 9,  dA1[3]*li8);
        float* o16 = out + r0 + (16 << 7) + col;
        atomicAdd(o16,     dB0[0]*li16); atomicAdd(o16 + 1, dB0[1]*li16);
        atomicAdd(o16 + 8, dB1[0]*li16); atomicAdd(o16 + 9, dB1[1]*li16);
        float* o24 = out + r0 + (24 << 7) + col;
        atomicAdd(o24,     dB0[2]*li24); atomicAdd(o24 + 1, dB0[3]*li24);
        atomicAdd(o24 + 8, dB1[2]*li24); atomicAdd(o24 + 9, dB1[3]*li24);
    }
}

extern "C" void kernel_launch(void* const* d_in, const int* in_sizes, int n_in,
                              void* d_out, int out_size)
{
    (void)in_sizes; (void)n_in; (void)out_size;
    const float* x   = (const float*)d_in[0];
    const int*   adj = (const int*)d_in[1];
    const float* ew  = (const float*)d_in[2];
    const float* W   = (const float*)d_in[3];
    const float* a   = (const float*)d_in[4];
    float* out = (float*)d_out;                   // [B,N,128]
    float* avg = out + (size_t)BB * NN * FOUT;    // [B,N,N]

    cudaFuncSetAttribute(gat_kB, cudaFuncAttributeMaxDynamicSharedMemorySize, SMEMB);

    gat_k1<<<BB * 32 * 2, 256>>>(x, W, a, out);
    gat_kA<<<dim3(NN / 32, BB, 2), 256>>>(adj);
    gat_kB<<<dim3(NN / TI, BB, 2), 256, SMEMB>>>(adj, ew, out, avg);
}